// round 14
// baseline (speedup 1.0000x reference)
#include <cuda_runtime.h>
#include <cuda_bf16.h>
#include <mma.h>
#include <cstddef>
#include <cstdint>

using namespace nvcuda;

__device__ float g_bufA[16u*64u*128u*128u];
__device__ float g_bufB[16u*128u*64u*64u];
__device__ float g_bufC[16u*128u*64u*64u];
__device__ float g_bufD[16u*128u*64u*64u];
__device__ float g_r  [16u*64u*64u*64u];
__device__ float g_q  [16u*64u*64u*64u];
__device__ float g_cnorm[4*512];
__device__ float g_partials[4*256];
__device__ __align__(16) __nv_bfloat16 g_act_hi[16u*4096u*128u];
__device__ __align__(16) __nv_bfloat16 g_act_lo[16u*4096u*128u];
__device__ __align__(16) __nv_bfloat16 g_wbh[9*128*128];
__device__ __align__(16) __nv_bfloat16 g_wbl[9*128*128];

__device__ __forceinline__ unsigned long long f2pack(float lo, float hi) {
    unsigned long long r; asm("mov.b64 %0, {%1, %2};" : "=l"(r) : "f"(lo), "f"(hi)); return r;
}
__device__ __forceinline__ unsigned long long ffma2(unsigned long long a, unsigned long long b, unsigned long long c) {
    unsigned long long d; asm("fma.rn.f32x2 %0, %1, %2, %3;" : "=l"(d) : "l"(a), "l"(b), "l"(c)); return d;
}
__device__ __forceinline__ float2 f2unpack(unsigned long long v) {
    float2 f; asm("mov.b64 {%0, %1}, %2;" : "=f"(f.x), "=f"(f.y) : "l"(v)); return f;
}
__device__ __forceinline__ void cp4(void* smem_dst, const void* gsrc, bool pred) {
    uint32_t s = (uint32_t)__cvta_generic_to_shared(smem_dst);
    int sz = pred ? 4 : 0;
    asm volatile("cp.async.ca.shared.global [%0], [%1], 4, %2;" :: "r"(s), "l"(gsrc), "r"(sz));
}
__device__ __forceinline__ void cp16(void* smem_dst, const void* gsrc, bool pred) {
    uint32_t s = (uint32_t)__cvta_generic_to_shared(smem_dst);
    int sz = pred ? 16 : 0;
    asm volatile("cp.async.cg.shared.global [%0], [%1], 16, %2;" :: "r"(s), "l"(gsrc), "r"(sz));
}
__device__ __forceinline__ void cp_commit() { asm volatile("cp.async.commit_group;"); }
template<int Nw> __device__ __forceinline__ void cp_wait() { asm volatile("cp.async.wait_group %0;" :: "n"(Nw)); }

// ---------------- NCHW fp32 -> NHWC bf16 hi/lo ----------------
__global__ __launch_bounds__(256)
void act_prep(const float* __restrict__ in, __nv_bfloat16* __restrict__ hi,
              __nv_bfloat16* __restrict__ lo, int C)
{
    __shared__ float tile[32][33];
    int n = blockIdx.z, pb = blockIdx.x*32, cb = blockIdx.y*32;
    int x = threadIdx.x & 31, ty = threadIdx.x >> 5;
    const float* ip = in + (size_t)n*C*4096;
    for (int cy = ty; cy < 32; cy += 8) tile[cy][x] = ip[(size_t)(cb+cy)*4096 + pb + x];
    __syncthreads();
    __nv_bfloat16* hp = hi + (size_t)n*4096*C;
    __nv_bfloat16* lp = lo + (size_t)n*4096*C;
    for (int py = ty; py < 32; py += 8) {
        float v = tile[x][py];
        __nv_bfloat16 h = __float2bfloat16(v);
        size_t o = (size_t)(pb+py)*C + cb + x;
        hp[o] = h; lp[o] = __float2bfloat16(v - __bfloat162float(h));
    }
}

// ---------------- weights [oc][ci][3][3] fp32 -> [tap][oc][ci] bf16 hi/lo ----------------
__global__ __launch_bounds__(256)
void wprep_bf(const float* __restrict__ w, __nv_bfloat16* __restrict__ hi,
              __nv_bfloat16* __restrict__ lo, int Cin, int total)
{
    int i = blockIdx.x*256 + threadIdx.x;
    if (i >= total) return;
    int ci = i % Cin, oc = (i / Cin) & 127, tap = i / (Cin*128);
    float v = w[((size_t)oc*Cin + ci)*9 + tap];
    __nv_bfloat16 h = __float2bfloat16(v);
    hi[i] = h;
    lo[i] = __float2bfloat16(v - __bfloat162float(h));
}

// ---------------- decoder 3x3 conv via wmma bf16 (2-term split, fp32 accum) ----------------
// Padded lead dimension LD = CIN+8 -> 272B/144B row stride (16 mod 128B): conflict-free
// fragment loads. Block: 128 oc x 128 px (2 image rows). B staged once w/ halo; A per tap.
template<int CIN>
__global__ __launch_bounds__(256, 1)
void conv3_wmma(const __nv_bfloat16* __restrict__ ahi, const __nv_bfloat16* __restrict__ alo,
                const __nv_bfloat16* __restrict__ whi, const __nv_bfloat16* __restrict__ wlo,
                const float* __restrict__ bias, float* __restrict__ out, int act)
{
    constexpr int LD  = CIN + 8;
    constexpr int BB  = 4*66*LD;       // elements per B split
    constexpr int AA  = 128*LD;        // elements per A split
    constexpr int CPR = CIN/8;         // 16B chunks per px/oc row
    constexpr int CLD = 136;           // fp32 epilogue pitch
    extern __shared__ char smem[];
    __nv_bfloat16* Bh = (__nv_bfloat16*)smem;
    __nv_bfloat16* Bl = Bh + BB;
    __nv_bfloat16* Ah = Bl + BB;
    __nv_bfloat16* Al = Ah + AA;
    float* Csm = (float*)smem;         // reused after compute

    const int tid = threadIdx.x, warp = tid >> 5;
    const int s = blockIdx.x, n = blockIdx.z;

    // stage B once: rows y = 2s-1 .. 2s+2, x = -1..64 (zero-filled OOB)
    {
        const __nv_bfloat16* src0 = ahi + (size_t)n*4096*CIN;
        const __nv_bfloat16* src1 = alo + (size_t)n*4096*CIN;
        for (int i = tid; i < 4*66*CPR; i += 256) {
            int pr = i / (66*CPR);
            int rem = i - pr*66*CPR;
            int xx = rem / CPR, ch = rem - xx*CPR;
            int y = 2*s - 1 + pr, gx = xx - 1;
            bool ok = ((unsigned)y < 64u) && ((unsigned)gx < 64u);
            size_t go = ((size_t)(y*64 + gx))*CIN + ch*8;
            int so = (pr*66 + xx)*LD + ch*8;
            cp16(Bh + so, src0 + go, ok);
            cp16(Bl + so, src1 + go, ok);
        }
        cp_commit();
    }

    wmma::fragment<wmma::accumulator, 16,16,16, float> acc[8];
    #pragma unroll
    for (int f = 0; f < 8; f++) wmma::fill_fragment(acc[f], 0.f);

    for (int t = 0; t < 9; t++) {
        __syncthreads();   // prior-tap readers done with Ah/Al
        for (int i = tid; i < 128*CPR; i += 256) {
            int oc = i / CPR, ch = i - oc*CPR;
            size_t go = ((size_t)t*128 + oc)*CIN + ch*8;
            int so = oc*LD + ch*8;
            cp16(Ah + so, whi + go, true);
            cp16(Al + so, wlo + go, true);
        }
        cp_commit();
        cp_wait<0>();
        __syncthreads();

        const int dy = t/3 - 1, dx = t%3 - 1;
        #pragma unroll
        for (int pass = 0; pass < 3; pass++) {
            const __nv_bfloat16* Ause = (pass == 2) ? Al : Ah;
            const __nv_bfloat16* Buse = (pass == 1) ? Bl : Bh;
            for (int k = 0; k < CIN/16; k++) {
                wmma::fragment<wmma::matrix_a, 16,16,16, __nv_bfloat16, wmma::row_major> af;
                wmma::load_matrix_sync(af, Ause + warp*16*LD + k*16, LD);
                #pragma unroll
                for (int nf = 0; nf < 8; nf++) {
                    int px0 = nf*16;
                    int prow = px0 >> 6, x0 = px0 & 63;
                    wmma::fragment<wmma::matrix_b, 16,16,16, __nv_bfloat16, wmma::col_major> bf;
                    wmma::load_matrix_sync(bf,
                        Buse + (size_t)((prow + dy + 1)*66 + (x0 + dx + 1))*LD + k*16, LD);
                    wmma::mma_sync(acc[nf], af, bf, acc[nf]);
                }
            }
        }
    }
    __syncthreads();       // all reads of A/B done -> reuse smem as C
    #pragma unroll
    for (int nf = 0; nf < 8; nf++)
        wmma::store_matrix_sync(Csm + warp*16*CLD + nf*16, acc[nf], CLD, wmma::mem_row_major);
    __syncthreads();

    for (int i = tid; i < 128*128; i += 256) {
        int oc = i >> 7, px = i & 127;
        float v = Csm[oc*CLD + px];
        if (bias) v += __ldg(bias + oc);
        if (act == 1)      v = (v > 0.f) ? v : 0.01f*v;
        else if (act == 2) v = (v > 0.f) ? v : 0.f;
        out[((size_t)n*128 + oc)*4096 + s*128 + px] = v;
    }
}

// -------- fp32 FFMA2 conv (ENCODER + e2; numerics locked) --------
template<int K, int S, int CIB>
__global__ __launch_bounds__(256, 2)
void conv_pipe(const float* __restrict__ in, const float* __restrict__ wt,
               const float* __restrict__ bias, const float* __restrict__ resid,
               float* __restrict__ out,
               int N, int Cin, int Hin, int Win, int Cout, int Hout, int Wout,
               int pad, int act)
{
    constexpr int IW  = 32*S + K - S;
    constexpr int IWP = IW | 1;
    constexpr int KK  = K*K;
    __shared__ float sIn[2][CIB*IW*IWP];
    __shared__ __align__(16) float sWt[2][CIB*KK*16];
    const int tid = threadIdx.x;
    const int chunks = Cout >> 4;
    const int n = blockIdx.z / chunks;
    const int ocb = (blockIdx.z - n*chunks) << 4;
    const int ox0 = blockIdx.x << 5, oy0 = blockIdx.y << 5;
    const int tx = tid & 15, ty = tid >> 4;
    const int ix0 = ox0*S - pad, iy0 = oy0*S - pad;
    const int HWin = Hin*Win;
    const float* inb = in + (size_t)n*Cin*HWin;
    const int tx2 = tid & 31, ty2 = tid >> 5;

    auto load_stage = [&](int cib, int buf) {
        #pragma unroll
        for (int cl = 0; cl < CIB; cl++) {
            const float* ip = inb + (size_t)(cib + cl)*HWin;
            float* sp = &sIn[buf][cl*IW*IWP];
            for (int r = ty2; r < IW; r += 8) {
                int gy = iy0 + r;
                bool rowok = (unsigned)gy < (unsigned)Hin;
                const float* rp = ip + (size_t)gy*Win;
                for (int c = tx2; c < IW; c += 32) {
                    int gx = ix0 + c;
                    cp4(sp + r*IWP + c, rp + gx, rowok && ((unsigned)gx < (unsigned)Win));
                }
            }
        }
        for (int i = tid; i < CIB*KK*16; i += 256) {
            int oc = i & 15, rest = i >> 4;
            int kk = rest % KK, cl = rest / KK;
            cp4(&sWt[buf][i], wt + ((size_t)(ocb+oc)*Cin + (cib+cl))*KK + kk, true);
        }
    };

    unsigned long long acc2[8][2][2];
    #pragma unroll
    for (int o = 0; o < 8; o++) { acc2[o][0][0]=0ull; acc2[o][0][1]=0ull; acc2[o][1][0]=0ull; acc2[o][1][1]=0ull; }

    const int NB = Cin / CIB;
    load_stage(0, 0); cp_commit();
    for (int b = 0; b < NB; b++) {
        const int buf = b & 1;
        if (b + 1 < NB) { load_stage((b+1)*CIB, buf ^ 1); cp_commit(); cp_wait<1>(); }
        else cp_wait<0>();
        __syncthreads();
        #pragma unroll
        for (int cl = 0; cl < CIB; cl++) {
            const float* sI = &sIn[buf][cl*IW*IWP];
            const float* sW = &sWt[buf][cl*KK*16];
            if constexpr (S == 1) {
                unsigned long long inr2[K+1][K+1];
                #pragma unroll
                for (int r = 0; r < K+1; r++)
                    #pragma unroll
                    for (int c = 0; c < K+1; c++) {
                        float v = sI[(ty*2 + r)*IWP + tx*2 + c];
                        inr2[r][c] = f2pack(v, v);
                    }
                #pragma unroll
                for (int ky = 0; ky < K; ky++)
                #pragma unroll
                for (int kx = 0; kx < K; kx++) {
                    const ulonglong2* wp2 = (const ulonglong2*)(sW + (ky*K + kx)*16);
                    ulonglong2 wa = wp2[0], wb = wp2[1], wc = wp2[2], wd = wp2[3];
                    unsigned long long w2[8] = {wa.x, wa.y, wb.x, wb.y, wc.x, wc.y, wd.x, wd.y};
                    #pragma unroll
                    for (int dy = 0; dy < 2; dy++)
                    #pragma unroll
                    for (int dx = 0; dx < 2; dx++) {
                        unsigned long long s2 = inr2[ky+dy][kx+dx];
                        #pragma unroll
                        for (int o = 0; o < 8; o++) acc2[o][dy][dx] = ffma2(w2[o], s2, acc2[o][dy][dx]);
                    }
                }
            } else {
                #pragma unroll
                for (int ky = 0; ky < K; ky++)
                #pragma unroll
                for (int kx = 0; kx < K; kx++) {
                    const ulonglong2* wp2 = (const ulonglong2*)(sW + (ky*K + kx)*16);
                    ulonglong2 wa = wp2[0], wb = wp2[1], wc = wp2[2], wd = wp2[3];
                    unsigned long long w2[8] = {wa.x, wa.y, wb.x, wb.y, wc.x, wc.y, wd.x, wd.y};
                    #pragma unroll
                    for (int dy = 0; dy < 2; dy++)
                    #pragma unroll
                    for (int dx = 0; dx < 2; dx++) {
                        float s = sI[((ty*2+dy)*S + ky)*IWP + (tx*2+dx)*S + kx];
                        unsigned long long s2 = f2pack(s, s);
                        #pragma unroll
                        for (int o = 0; o < 8; o++) acc2[o][dy][dx] = ffma2(w2[o], s2, acc2[o][dy][dx]);
                    }
                }
            }
        }
        __syncthreads();
    }

    float acc[16][2][2];
    #pragma unroll
    for (int o = 0; o < 8; o++)
    #pragma unroll
    for (int dy = 0; dy < 2; dy++)
    #pragma unroll
    for (int dx = 0; dx < 2; dx++) {
        float2 f = f2unpack(acc2[o][dy][dx]);
        acc[2*o][dy][dx] = f.x; acc[2*o+1][dy][dx] = f.y;
    }
    const int oy = oy0 + ty*2, ox = ox0 + tx*2;
    #pragma unroll
    for (int o = 0; o < 16; o++) {
        int c = ocb + o;
        float bv = bias ? __ldg(bias + c) : 0.f;
        #pragma unroll
        for (int dy = 0; dy < 2; dy++)
        #pragma unroll
        for (int dx = 0; dx < 2; dx++) {
            float v = acc[o][dy][dx];
            if (bias)  v = __fadd_rn(v, bv);
            size_t oi = (((size_t)n*Cout + c)*Hout + (oy+dy))*Wout + (ox+dx);
            if (resid) v = __fadd_rn(v, resid[oi]);
            if (act == 1)      v = (v > 0.f) ? v : __fmul_rn(0.01f, v);
            else if (act == 2) v = (v > 0.f) ? v : 0.f;
            out[oi] = v;
        }
    }
}

__global__ __launch_bounds__(256)
void conv1x1(const float* __restrict__ in, const float* __restrict__ wt,
             const float* __restrict__ bias, const float* __restrict__ resid,
             float* __restrict__ out, int Cin, int HW, int Cout, int act)
{
    __shared__ __align__(16) float sW[128*16];
    const int tid = threadIdx.x;
    const int ocb = blockIdx.y << 4;
    for (int i = tid; i < Cin*16; i += 256) {
        int oc = i & 15, ci = i >> 4;
        sW[i] = __ldg(wt + (size_t)(ocb+oc)*Cin + ci);
    }
    __syncthreads();
    const int gp = (blockIdx.x*256 + tid) * 4;
    const int n = gp / HW, p = gp - n*HW;
    const float* ip = in + ((size_t)n*Cin)*HW + p;
    unsigned long long acc2[8][4];
    #pragma unroll
    for (int o = 0; o < 8; o++)
        #pragma unroll
        for (int j = 0; j < 4; j++) acc2[o][j] = 0ull;
    #pragma unroll 2
    for (int ci = 0; ci < Cin; ci++) {
        float4 xv = *(const float4*)(ip + (size_t)ci*HW);
        unsigned long long xp[4] = { f2pack(xv.x,xv.x), f2pack(xv.y,xv.y), f2pack(xv.z,xv.z), f2pack(xv.w,xv.w) };
        const ulonglong2* wp2 = (const ulonglong2*)(sW + ci*16);
        ulonglong2 wa = wp2[0], wb = wp2[1], wc = wp2[2], wd = wp2[3];
        unsigned long long w2[8] = {wa.x, wa.y, wb.x, wb.y, wc.x, wc.y, wd.x, wd.y};
        #pragma unroll
        for (int o = 0; o < 8; o++) {
            acc2[o][0] = ffma2(w2[o], xp[0], acc2[o][0]);
            acc2[o][1] = ffma2(w2[o], xp[1], acc2[o][1]);
            acc2[o][2] = ffma2(w2[o], xp[2], acc2[o][2]);
            acc2[o][3] = ffma2(w2[o], xp[3], acc2[o][3]);
        }
    }
    #pragma unroll
    for (int o2 = 0; o2 < 8; o2++) {
        float accl[2][4];
        #pragma unroll
        for (int j = 0; j < 4; j++) { float2 f = f2unpack(acc2[o2][j]); accl[0][j] = f.x; accl[1][j] = f.y; }
        #pragma unroll
        for (int h = 0; h < 2; h++) {
            int c = ocb + 2*o2 + h;
            float bv = bias ? __ldg(bias + c) : 0.f;
            size_t ob = ((size_t)n*Cout + c)*HW + p;
            #pragma unroll
            for (int j = 0; j < 4; j++) {
                float v = accl[h][j];
                if (bias)  v = __fadd_rn(v, bv);
                if (resid) v = __fadd_rn(v, resid[ob + j]);
                if (act == 1)      v = (v > 0.f) ? v : __fmul_rn(0.01f, v);
                else if (act == 2) v = (v > 0.f) ? v : 0.f;
                out[ob + j] = v;
            }
        }
    }
}

template<int OCBt, int LOG_OCB, int CIB>
__global__ __launch_bounds__(256, 2)
void convT_pipe(const float* __restrict__ in, const float* __restrict__ wt,
                const float* __restrict__ bias, float* __restrict__ out,
                int N, int Cin, int Hin, int Win, int Cout, int act)
{
    constexpr int IW = 18, IWP = 19, OP = OCBt/2;
    __shared__ float sIn[2][CIB*IW*IWP];
    __shared__ __align__(16) float sWt[2][CIB*16*OCBt];
    const int tid = threadIdx.x;
    const int Hout = Hin*2, Wout = Win*2;
    const int chunks = Cout >> LOG_OCB;
    const int n = blockIdx.z / chunks;
    const int ocb = (blockIdx.z - n*chunks) << LOG_OCB;
    const int ox0 = blockIdx.x << 5, oy0 = blockIdx.y << 5;
    const int tx = tid & 15, ty = tid >> 4;
    const int iyb = (oy0 >> 1) - 1, ixb = (ox0 >> 1) - 1;
    const int HWin = Hin*Win;
    const float* inb = in + (size_t)n*Cin*HWin;
    const int tx2 = tid & 31, ty2 = tid >> 5;
    const int ky0 = 1 - (ty & 1), kx0 = 1 - (tx & 1);
    const int hy = (ty >> 1) + 1 + (ty & 1);
    const int hx = (tx >> 1) + 1 + (tx & 1);

    auto load_stage = [&](int cib, int buf) {
        #pragma unroll
        for (int cl = 0; cl < CIB; cl++) {
            const float* ip = inb + (size_t)(cib + cl)*HWin;
            float* sp = &sIn[buf][cl*IW*IWP];
            for (int r = ty2; r < IW; r += 8) {
                int gy = iyb + r;
                bool rowok = (unsigned)gy < (unsigned)Hin;
                const float* rp = ip + (size_t)gy*Win;
                for (int c = tx2; c < IW; c += 32) {
                    int gx = ixb + c;
                    cp4(sp + r*IWP + c, rp + gx, rowok && ((unsigned)gx < (unsigned)Win));
                }
            }
        }
        for (int i = tid; i < CIB*16*OCBt; i += 256) {
            int oc = i & (OCBt-1), rest = i >> LOG_OCB;
            int kk = rest & 15, cl = rest >> 4;
            cp4(&sWt[buf][i], wt + ((size_t)(cib+cl)*Cout + (ocb+oc))*16 + kk, true);
        }
    };

    unsigned long long acc2[OP][2][2];
    #pragma unroll
    for (int o = 0; o < OP; o++) { acc2[o][0][0]=0ull; acc2[o][0][1]=0ull; acc2[o][1][0]=0ull; acc2[o][1][1]=0ull; }

    const int NB = Cin / CIB;
    load_stage(0, 0); cp_commit();
    for (int b = 0; b < NB; b++) {
        const int buf = b & 1;
        if (b + 1 < NB) { load_stage((b+1)*CIB, buf ^ 1); cp_commit(); cp_wait<1>(); }
        else cp_wait<0>();
        __syncthreads();
        #pragma unroll
        for (int cl = 0; cl < CIB; cl++) {
            const float* sI = &sIn[buf][cl*IW*IWP];
            const float* sW = &sWt[buf][cl*16*OCBt];
            unsigned long long vin2[2][2][2][2];
            #pragma unroll
            for (int ey = 0; ey < 2; ey++)
            #pragma unroll
            for (int tyt = 0; tyt < 2; tyt++)
            #pragma unroll
            for (int ex = 0; ex < 2; ex++)
            #pragma unroll
            for (int txt = 0; txt < 2; txt++) {
                float v = sI[(hy + 8*ey - tyt)*IWP + (hx + 8*ex - txt)];
                vin2[ey][tyt][ex][txt] = f2pack(v, v);
            }
            #pragma unroll
            for (int tyt = 0; tyt < 2; tyt++)
            #pragma unroll
            for (int txt = 0; txt < 2; txt++) {
                const int kk = (ky0 + 2*tyt)*4 + (kx0 + 2*txt);
                const unsigned long long* wp2 = (const unsigned long long*)(sW + kk*OCBt);
                unsigned long long w2[OP];
                #pragma unroll
                for (int j = 0; j < OP; j++) w2[j] = wp2[j];
                #pragma unroll
                for (int ey = 0; ey < 2; ey++)
                #pragma unroll
                for (int ex = 0; ex < 2; ex++) {
                    unsigned long long s2 = vin2[ey][tyt][ex][txt];
                    #pragma unroll
                    for (int o = 0; o < OP; o++) acc2[o][ey][ex] = ffma2(w2[o], s2, acc2[o][ey][ex]);
                }
            }
        }
        __syncthreads();
    }
    #pragma unroll
    for (int o2 = 0; o2 < OP; o2++) {
        float accl[2][2][2];
        #pragma unroll
        for (int ey = 0; ey < 2; ey++)
        #pragma unroll
        for (int ex = 0; ex < 2; ex++) {
            float2 f = f2unpack(acc2[o2][ey][ex]);
            accl[0][ey][ex] = f.x; accl[1][ey][ex] = f.y;
        }
        #pragma unroll
        for (int h = 0; h < 2; h++) {
            int c = ocb + 2*o2 + h;
            float bv = bias ? __ldg(bias + c) : 0.f;
            #pragma unroll
            for (int ey = 0; ey < 2; ey++)
            #pragma unroll
            for (int ex = 0; ex < 2; ex++) {
                float v = accl[h][ey][ex];
                if (bias) v = __fadd_rn(v, bv);
                int oy = oy0 + ty + 16*ey, ox = ox0 + tx + 16*ex;
                if (act == 1)      v = (v > 0.f) ? v : __fmul_rn(0.01f, v);
                else if (act == 2) v = (v > 0.f) ? v : 0.f;
                out[(((size_t)n*Cout + c)*Hout + oy)*Wout + ox] = v;
            }
        }
    }
}

// -------- RVQ (numerics locked) --------
__global__ __launch_bounds__(256)
void cnorm_kernel(const float* __restrict__ cb, float* __restrict__ cn, int total)
{
    int warp = (blockIdx.x*256 + threadIdx.x) >> 5;
    int lane = threadIdx.x & 31;
    if (warp >= total) return;
    const float* p = cb + (size_t)warp*64;
    float a0 = p[lane], a1 = p[lane+32];
    float a = __fadd_rn(__fmul_rn(a0, a0), __fmul_rn(a1, a1));
    #pragma unroll
    for (int off = 16; off > 0; off >>= 1) a = __fadd_rn(a, __shfl_down_sync(0xffffffffu, a, off));
    if (lane == 0) cn[warp] = a;
}

__global__ __launch_bounds__(256)
void rvq_fused(const float* __restrict__ r_in, float* __restrict__ qacc,
               const float* __restrict__ cbs, const float* __restrict__ cnorm,
               float* __restrict__ idx_out, float* __restrict__ partials, int HW)
{
    __shared__ __align__(16) float sCt[64*32];
    __shared__ float sCn[32];
    __shared__ float sRed[256];
    const int t = blockIdx.x*256 + threadIdx.x;
    const int n = t / HW, p = t - n*HW;
    const size_t base = (size_t)n*64*HW + p;
    float rl[64], qa[64];
    #pragma unroll
    for (int d = 0; d < 64; d++) rl[d] = r_in[base + (size_t)d*HW];

    for (int stage = 0; stage < 4; stage++) {
        const float* cb = cbs + (size_t)stage*512*64;
        const float* cn = cnorm + stage*512;
        float rn = 0.f;
        #pragma unroll
        for (int d = 0; d < 64; d++) rn = fmaf(rl[d], rl[d], rn);
        float best = 3.4e38f; int bidx = 0;
        for (int kb = 0; kb < 512; kb += 32) {
            __syncthreads();
            for (int i = threadIdx.x; i < 64*32; i += 256) {
                int kk = i & 31, d = i >> 5;
                sCt[i] = __ldg(cb + (size_t)(kb + kk)*64 + d);
            }
            if (threadIdx.x < 32) sCn[threadIdx.x] = cn[kb + threadIdx.x];
            __syncthreads();
            unsigned long long dot2[16];
            #pragma unroll
            for (int j = 0; j < 16; j++) dot2[j] = 0ull;
            #pragma unroll
            for (int d = 0; d < 64; d++) {
                unsigned long long rt2 = f2pack(rl[d], rl[d]);
                const ulonglong2* cp = (const ulonglong2*)(sCt + d*32);
                #pragma unroll
                for (int j4 = 0; j4 < 8; j4++) {
                    ulonglong2 c2 = cp[j4];
                    dot2[j4*2+0] = ffma2(rt2, c2.x, dot2[j4*2+0]);
                    dot2[j4*2+1] = ffma2(rt2, c2.y, dot2[j4*2+1]);
                }
            }
            #pragma unroll
            for (int j2 = 0; j2 < 16; j2++) {
                float2 dd = f2unpack(dot2[j2]);
                float dist0 = __fadd_rn(__fadd_rn(rn, -__fmul_rn(2.f, dd.x)), sCn[2*j2]);
                if (dist0 < best) { best = dist0; bidx = kb + 2*j2; }
                float dist1 = __fadd_rn(__fadd_rn(rn, -__fmul_rn(2.f, dd.y)), sCn[2*j2+1]);
                if (dist1 < best) { best = dist1; bidx = kb + 2*j2 + 1; }
            }
        }
        float lsum = 0.f;
        const float* cq = cb + (size_t)bidx*64;
        #pragma unroll
        for (int d = 0; d < 64; d++) {
            float q = __ldg(cq + d);
            float diff = __fadd_rn(q, -rl[d]);
            lsum = fmaf(diff, diff, lsum);
            float q_st = __fadd_rn(rl[d], diff);
            if (stage == 0) qa[d] = q_st;
            else            qa[d] = __fadd_rn(qa[d], q_st);
            rl[d] = __fadd_rn(rl[d], -q);
        }
        idx_out[(size_t)t*4 + stage] = (float)bidx;
        __syncthreads();
        sRed[threadIdx.x] = lsum;
        __syncthreads();
        for (int sft = 128; sft > 0; sft >>= 1) {
            if (threadIdx.x < sft) sRed[threadIdx.x] += sRed[threadIdx.x + sft];
            __syncthreads();
        }
        if (threadIdx.x == 0) partials[stage*256 + blockIdx.x] = sRed[0];
    }
    #pragma unroll
    for (int d = 0; d < 64; d++) qacc[base + (size_t)d*HW] = qa[d];
}

__global__ __launch_bounds__(256)
void loss_finalize(const float* __restrict__ partials, float* __restrict__ loss_out, float scale)
{
    __shared__ float sRed[256];
    int stage = blockIdx.x;
    sRed[threadIdx.x] = partials[stage*256 + threadIdx.x];
    __syncthreads();
    for (int sft = 128; sft > 0; sft >>= 1) {
        if (threadIdx.x < sft) sRed[threadIdx.x] += sRed[threadIdx.x + sft];
        __syncthreads();
    }
    if (threadIdx.x == 0) loss_out[stage] = 0.25f * (sRed[0] * scale);
}

extern "C" void kernel_launch(void* const* d_in, const int* in_sizes, int n_in,
                              void* d_out, int out_size)
{
    const float* x     = (const float*)d_in[0];
    const float* e1w   = (const float*)d_in[1];
    const float* e1b   = (const float*)d_in[2];
    const float* e2w   = (const float*)d_in[3];
    const float* e2b   = (const float*)d_in[4];
    const float* e3w   = (const float*)d_in[5];
    const float* e3b   = (const float*)d_in[6];
    const float* r1aw  = (const float*)d_in[7];
    const float* r1bw  = (const float*)d_in[8];
    const float* r2aw  = (const float*)d_in[9];
    const float* r2bw  = (const float*)d_in[10];
    const float* e4w   = (const float*)d_in[11];
    const float* e4b   = (const float*)d_in[12];
    const float* cbs   = (const float*)d_in[13];
    const float* d1w   = (const float*)d_in[14];
    const float* d1b   = (const float*)d_in[15];
    const float* dr1aw = (const float*)d_in[16];
    const float* dr1bw = (const float*)d_in[17];
    const float* dr2aw = (const float*)d_in[18];
    const float* dr2bw = (const float*)d_in[19];
    const float* dt1w  = (const float*)d_in[20];
    const float* dt1b  = (const float*)d_in[21];
    const float* dt2w  = (const float*)d_in[22];
    const float* dt2b  = (const float*)d_in[23];

    float* out = (float*)d_out;
    float* recons  = out;
    float* idxout  = out + (size_t)16*4*256*256;
    float* lossout = idxout + (size_t)16*64*64*4;

    float *A,*B,*C,*D,*R,*Q,*CN,*P;
    __nv_bfloat16 *AH,*AL,*WBH,*WBL;
    cudaGetSymbolAddress((void**)&A,  g_bufA);
    cudaGetSymbolAddress((void**)&B,  g_bufB);
    cudaGetSymbolAddress((void**)&C,  g_bufC);
    cudaGetSymbolAddress((void**)&D,  g_bufD);
    cudaGetSymbolAddress((void**)&R,  g_r);
    cudaGetSymbolAddress((void**)&Q,  g_q);
    cudaGetSymbolAddress((void**)&CN, g_cnorm);
    cudaGetSymbolAddress((void**)&P,  g_partials);
    cudaGetSymbolAddress((void**)&AH, g_act_hi);
    cudaGetSymbolAddress((void**)&AL, g_act_lo);
    cudaGetSymbolAddress((void**)&WBH, g_wbh);
    cudaGetSymbolAddress((void**)&WBL, g_wbl);

    const int SM128 = (2*(4*66*136) + 2*(128*136)) * 2;   // 213,248 B
    const int SM64  = (2*(4*66*72)  + 2*(128*72))  * 2;   // 112,896 B
    cudaFuncSetAttribute(conv3_wmma<128>, cudaFuncAttributeMaxDynamicSharedMemorySize, SM128);
    cudaFuncSetAttribute(conv3_wmma<64>,  cudaFuncAttributeMaxDynamicSharedMemorySize, SM64);

    cnorm_kernel<<<256, 256>>>(cbs, CN, 4*512);

    // encoder (fp32, locked)
    conv_pipe<4,2,1><<<dim3(4,4,64), 256>>>(x, e1w, e1b, nullptr, A, 16,4,256,256, 64,128,128, 1, 1);
    conv_pipe<4,2,1><<<dim3(2,2,128), 256>>>(A, e2w, e2b, nullptr, B, 16,64,128,128, 128,64,64, 1, 1);
    conv_pipe<3,1,4><<<dim3(2,2,128), 256>>>(B, e3w, e3b, nullptr, C, 16,128,64,64, 128,64,64, 1, 1);
    conv_pipe<3,1,4><<<dim3(2,2,128), 256>>>(C, r1aw, nullptr, nullptr, D, 16,128,64,64, 128,64,64, 1, 2);
    conv1x1<<<dim3(64,8), 256>>>(D, r1bw, nullptr, C, B, 128, 4096, 128, 0);
    conv_pipe<3,1,4><<<dim3(2,2,128), 256>>>(B, r2aw, nullptr, nullptr, D, 16,128,64,64, 128,64,64, 1, 2);
    conv1x1<<<dim3(64,8), 256>>>(D, r2bw, nullptr, B, C, 128, 4096, 128, 1);
    conv1x1<<<dim3(64,4), 256>>>(C, e4w, e4b, nullptr, R, 128, 4096, 64, 1);

    // RVQ
    rvq_fused<<<256, 256>>>(R, Q, cbs, CN, idxout, P, 64*64);
    loss_finalize<<<4, 256>>>(P, lossout, 1.f/(65536.f*64.f));

    // decoder: 3x3 convs on wmma bf16 tensor cores (2-term split, padded smem)
    act_prep<<<dim3(128,2,16), 256>>>(Q, AH, AL, 64);
    wprep_bf<<<(9*128*64+255)/256, 256>>>(d1w, WBH, WBL, 64, 9*128*64);
    conv3_wmma<64><<<dim3(32,1,16), 256, SM64>>>(AH, AL, WBH, WBL, d1b, B, 1);

    act_prep<<<dim3(128,4,16), 256>>>(B, AH, AL, 128);
    wprep_bf<<<(9*128*128+255)/256, 256>>>(dr1aw, WBH, WBL, 128, 9*128*128);
    conv3_wmma<128><<<dim3(32,1,16), 256, SM128>>>(AH, AL, WBH, WBL, nullptr, D, 2);
    conv1x1<<<dim3(64,8), 256>>>(D, dr1bw, nullptr, B, C, 128, 4096, 128, 0);

    act_prep<<<dim3(128,4,16), 256>>>(C, AH, AL, 128);
    wprep_bf<<<(9*128*128+255)/256, 256>>>(dr2aw, WBH, WBL, 128, 9*128*128);
    conv3_wmma<128><<<dim3(32,1,16), 256, SM128>>>(AH, AL, WBH, WBL, nullptr, D, 2);
    conv1x1<<<dim3(64,8), 256>>>(D, dr2bw, nullptr, C, B, 128, 4096, 128, 1);

    convT_pipe<16,4,8><<<dim3(4,4,64), 256>>>(B, dt1w, dt1b, A, 16,128,64,64, 64, 1);
    convT_pipe<4,2,8><<<dim3(8,8,16), 256>>>(A, dt2w, dt2b, recons, 16,64,128,128, 4, 2);
}

// round 17
// speedup vs baseline: 1.6152x; 1.6152x over previous
#include <cuda_runtime.h>
#include <cuda_bf16.h>
#include <cstddef>
#include <cstdint>

// ---------------- scratch (device globals; no allocation allowed) ----------------
__device__ float g_bufA[16u*64u*128u*128u];   // 16.78M floats (e1 out / dt1 out)
__device__ float g_bufB[16u*128u*64u*64u];    // 8.39M
__device__ float g_bufC[16u*128u*64u*64u];
__device__ float g_bufD[16u*128u*64u*64u];
__device__ float g_r  [16u*64u*64u*64u];      // residual tokens (NCHW view)
__device__ float g_q  [16u*64u*64u*64u];      // quantized accumulation (NCHW view)
__device__ float g_cnorm[4*512];
__device__ float g_partials[4*256];

// ---------------- packed fp32x2 helpers (two independent IEEE fp32 lanes) ----------------
__device__ __forceinline__ unsigned long long f2pack(float lo, float hi) {
    unsigned long long r;
    asm("mov.b64 %0, {%1, %2};" : "=l"(r) : "f"(lo), "f"(hi));
    return r;
}
__device__ __forceinline__ unsigned long long ffma2(unsigned long long a,
                                                    unsigned long long b,
                                                    unsigned long long c) {
    unsigned long long d;
    asm("fma.rn.f32x2 %0, %1, %2, %3;" : "=l"(d) : "l"(a), "l"(b), "l"(c));
    return d;
}
__device__ __forceinline__ float2 f2unpack(unsigned long long v) {
    float2 f;
    asm("mov.b64 {%0, %1}, %2;" : "=f"(f.x), "=f"(f.y) : "l"(v));
    return f;
}

// ---------------- cp.async helpers ----------------
__device__ __forceinline__ void cp4(void* smem_dst, const void* gsrc, bool pred) {
    uint32_t s = (uint32_t)__cvta_generic_to_shared(smem_dst);
    int sz = pred ? 4 : 0;               // src-size 0 -> zero-fill (free OOB padding)
    asm volatile("cp.async.ca.shared.global [%0], [%1], 4, %2;" :: "r"(s), "l"(gsrc), "r"(sz));
}
__device__ __forceinline__ void cp_commit() {
    asm volatile("cp.async.commit_group;");
}
template<int Nw>
__device__ __forceinline__ void cp_wait() {
    asm volatile("cp.async.wait_group %0;" :: "n"(Nw));
}

// ---------------- pipelined register-tiled direct convolution (fp32; numerics locked) ----------
// Per-output accumulation: ci asc, (ky,kx) asc, single fma chain per output.
// FFMA2 packs oc pairs: each half-lane chain is bit-identical to the scalar version.
template<int K, int S, int CIB>
__global__ __launch_bounds__(256, 2)
void conv_pipe(const float* __restrict__ in, const float* __restrict__ wt,
               const float* __restrict__ bias, const float* __restrict__ resid,
               float* __restrict__ out,
               int N, int Cin, int Hin, int Win, int Cout, int Hout, int Wout,
               int pad, int act)
{
    constexpr int IW  = 32*S + K - S;
    constexpr int IWP = IW | 1;
    constexpr int KK  = K*K;
    __shared__ float sIn[2][CIB*IW*IWP];
    __shared__ __align__(16) float sWt[2][CIB*KK*16];

    const int tid = threadIdx.x;
    const int chunks = Cout >> 4;
    const int n   = blockIdx.z / chunks;
    const int ocb = (blockIdx.z - n*chunks) << 4;
    const int ox0 = blockIdx.x << 5, oy0 = blockIdx.y << 5;
    const int tx = tid & 15, ty = tid >> 4;
    const int ix0 = ox0*S - pad, iy0 = oy0*S - pad;
    const int HWin = Hin*Win;
    const float* inb = in + (size_t)n*Cin*HWin;
    const int tx2 = tid & 31, ty2 = tid >> 5;

    auto load_stage = [&](int cib, int buf) {
        #pragma unroll
        for (int cl = 0; cl < CIB; cl++) {
            const float* ip = inb + (size_t)(cib + cl)*HWin;
            float* sp = &sIn[buf][cl*IW*IWP];
            for (int r = ty2; r < IW; r += 8) {
                int gy = iy0 + r;
                bool rowok = (unsigned)gy < (unsigned)Hin;
                const float* rp = ip + (size_t)gy*Win;
                for (int c = tx2; c < IW; c += 32) {
                    int gx = ix0 + c;
                    cp4(sp + r*IWP + c, rp + gx,
                        rowok && ((unsigned)gx < (unsigned)Win));
                }
            }
        }
        for (int i = tid; i < CIB*KK*16; i += 256) {
            int oc = i & 15;
            int rest = i >> 4;
            int kk = rest % KK, cl = rest / KK;
            cp4(&sWt[buf][i], wt + ((size_t)(ocb+oc)*Cin + (cib+cl))*KK + kk, true);
        }
    };

    unsigned long long acc2[8][2][2];
    #pragma unroll
    for (int o = 0; o < 8; o++) {
        acc2[o][0][0] = 0ull; acc2[o][0][1] = 0ull;
        acc2[o][1][0] = 0ull; acc2[o][1][1] = 0ull;
    }

    const int NB = Cin / CIB;
    load_stage(0, 0);
    cp_commit();

    for (int b = 0; b < NB; b++) {
        const int buf = b & 1;
        if (b + 1 < NB) {
            load_stage((b+1)*CIB, buf ^ 1);
            cp_commit();
            cp_wait<1>();
        } else {
            cp_wait<0>();
        }
        __syncthreads();

        #pragma unroll
        for (int cl = 0; cl < CIB; cl++) {
            const float* sI = &sIn[buf][cl*IW*IWP];
            const float* sW = &sWt[buf][cl*KK*16];
            if constexpr (S == 1) {
                unsigned long long inr2[K+1][K+1];
                #pragma unroll
                for (int r = 0; r < K+1; r++)
                    #pragma unroll
                    for (int c = 0; c < K+1; c++) {
                        float v = sI[(ty*2 + r)*IWP + tx*2 + c];
                        inr2[r][c] = f2pack(v, v);
                    }
                #pragma unroll
                for (int ky = 0; ky < K; ky++)
                #pragma unroll
                for (int kx = 0; kx < K; kx++) {
                    const ulonglong2* wp = (const ulonglong2*)(sW + (ky*K + kx)*16);
                    ulonglong2 wa = wp[0], wb = wp[1], wc = wp[2], wd = wp[3];
                    unsigned long long w2[8] = {wa.x, wa.y, wb.x, wb.y,
                                                wc.x, wc.y, wd.x, wd.y};
                    #pragma unroll
                    for (int dy = 0; dy < 2; dy++)
                    #pragma unroll
                    for (int dx = 0; dx < 2; dx++) {
                        unsigned long long s2 = inr2[ky+dy][kx+dx];
                        #pragma unroll
                        for (int o = 0; o < 8; o++)
                            acc2[o][dy][dx] = ffma2(w2[o], s2, acc2[o][dy][dx]);
                    }
                }
            } else {
                #pragma unroll
                for (int ky = 0; ky < K; ky++)
                #pragma unroll
                for (int kx = 0; kx < K; kx++) {
                    const ulonglong2* wp = (const ulonglong2*)(sW + (ky*K + kx)*16);
                    ulonglong2 wa = wp[0], wb = wp[1], wc = wp[2], wd = wp[3];
                    unsigned long long w2[8] = {wa.x, wa.y, wb.x, wb.y,
                                                wc.x, wc.y, wd.x, wd.y};
                    #pragma unroll
                    for (int dy = 0; dy < 2; dy++)
                    #pragma unroll
                    for (int dx = 0; dx < 2; dx++) {
                        float s = sI[((ty*2+dy)*S + ky)*IWP + (tx*2+dx)*S + kx];
                        unsigned long long s2 = f2pack(s, s);
                        #pragma unroll
                        for (int o = 0; o < 8; o++)
                            acc2[o][dy][dx] = ffma2(w2[o], s2, acc2[o][dy][dx]);
                    }
                }
            }
        }
        __syncthreads();
    }

    float acc[16][2][2];
    #pragma unroll
    for (int o = 0; o < 8; o++)
    #pragma unroll
    for (int dy = 0; dy < 2; dy++)
    #pragma unroll
    for (int dx = 0; dx < 2; dx++) {
        float2 f = f2unpack(acc2[o][dy][dx]);
        acc[2*o  ][dy][dx] = f.x;
        acc[2*o+1][dy][dx] = f.y;
    }

    const int oy = oy0 + ty*2, ox = ox0 + tx*2;
    #pragma unroll
    for (int o = 0; o < 16; o++) {
        int c = ocb + o;
        float bv = bias ? __ldg(bias + c) : 0.f;
        #pragma unroll
        for (int dy = 0; dy < 2; dy++)
        #pragma unroll
        for (int dx = 0; dx < 2; dx++) {
            float v = acc[o][dy][dx];
            if (bias)  v = __fadd_rn(v, bv);
            size_t oi = (((size_t)n*Cout + c)*Hout + (oy+dy))*Wout + (ox+dx);
            if (resid) v = __fadd_rn(v, resid[oi]);
            if (act == 1)      v = (v > 0.f) ? v : __fmul_rn(0.01f, v);
            else if (act == 2) v = (v > 0.f) ? v : 0.f;
            out[oi] = v;
        }
    }
}

// ---------------- direct 1x1 convolution (GEMM-style, FFMA2-packed) ----------------
__global__ __launch_bounds__(256)
void conv1x1(const float* __restrict__ in, const float* __restrict__ wt,
             const float* __restrict__ bias, const float* __restrict__ resid,
             float* __restrict__ out,
             int Cin, int HW, int Cout, int act)
{
    __shared__ __align__(16) float sW[128*16];   // [ci][oc], Cin<=128

    const int tid = threadIdx.x;
    const int ocb = blockIdx.y << 4;
    for (int i = tid; i < Cin*16; i += 256) {
        int oc = i & 15, ci = i >> 4;
        sW[i] = __ldg(wt + (size_t)(ocb+oc)*Cin + ci);
    }
    __syncthreads();

    const int gp = (blockIdx.x*256 + tid) * 4;
    const int n = gp / HW, p = gp - n*HW;
    const float* ip = in + ((size_t)n*Cin)*HW + p;

    unsigned long long acc2[8][4];
    #pragma unroll
    for (int o = 0; o < 8; o++)
        #pragma unroll
        for (int j = 0; j < 4; j++) acc2[o][j] = 0ull;

    #pragma unroll 2
    for (int ci = 0; ci < Cin; ci++) {
        float4 xv = *(const float4*)(ip + (size_t)ci*HW);
        unsigned long long xp[4] = { f2pack(xv.x, xv.x), f2pack(xv.y, xv.y),
                                     f2pack(xv.z, xv.z), f2pack(xv.w, xv.w) };
        const ulonglong2* wp = (const ulonglong2*)(sW + ci*16);
        ulonglong2 wa = wp[0], wb = wp[1], wc = wp[2], wd = wp[3];
        unsigned long long w2[8] = {wa.x, wa.y, wb.x, wb.y, wc.x, wc.y, wd.x, wd.y};
        #pragma unroll
        for (int o = 0; o < 8; o++) {
            acc2[o][0] = ffma2(w2[o], xp[0], acc2[o][0]);
            acc2[o][1] = ffma2(w2[o], xp[1], acc2[o][1]);
            acc2[o][2] = ffma2(w2[o], xp[2], acc2[o][2]);
            acc2[o][3] = ffma2(w2[o], xp[3], acc2[o][3]);
        }
    }

    #pragma unroll
    for (int o2 = 0; o2 < 8; o2++) {
        float accl[2][4];
        #pragma unroll
        for (int j = 0; j < 4; j++) {
            float2 f = f2unpack(acc2[o2][j]);
            accl[0][j] = f.x; accl[1][j] = f.y;
        }
        #pragma unroll
        for (int h = 0; h < 2; h++) {
            int c = ocb + 2*o2 + h;
            float bv = bias ? __ldg(bias + c) : 0.f;
            size_t ob = ((size_t)n*Cout + c)*HW + p;
            #pragma unroll
            for (int j = 0; j < 4; j++) {
                float v = accl[h][j];
                if (bias)  v = __fadd_rn(v, bv);
                if (resid) v = __fadd_rn(v, resid[ob + j]);
                if (act == 1)      v = (v > 0.f) ? v : __fmul_rn(0.01f, v);
                else if (act == 2) v = (v > 0.f) ? v : 0.f;
                out[ob + j] = v;
            }
        }
    }
}

// ---------------- pipelined transposed conv (k=4,s=2,p=1), FFMA2-packed ----------------
template<int OCBt, int LOG_OCB, int CIB>
__global__ __launch_bounds__(256, 2)
void convT_pipe(const float* __restrict__ in, const float* __restrict__ wt,
                const float* __restrict__ bias, float* __restrict__ out,
                int N, int Cin, int Hin, int Win, int Cout, int act)
{
    constexpr int IW = 18, IWP = 19;
    constexpr int OP = OCBt/2;   // oc pairs
    __shared__ float sIn[2][CIB*IW*IWP];
    __shared__ __align__(16) float sWt[2][CIB*16*OCBt];

    const int tid = threadIdx.x;
    const int Hout = Hin*2, Wout = Win*2;
    const int chunks = Cout >> LOG_OCB;
    const int n   = blockIdx.z / chunks;
    const int ocb = (blockIdx.z - n*chunks) << LOG_OCB;
    const int ox0 = blockIdx.x << 5, oy0 = blockIdx.y << 5;
    const int tx = tid & 15, ty = tid >> 4;
    const int iyb = (oy0 >> 1) - 1, ixb = (ox0 >> 1) - 1;
    const int HWin = Hin*Win;
    const float* inb = in + (size_t)n*Cin*HWin;
    const int tx2 = tid & 31, ty2 = tid >> 5;

    const int ky0 = 1 - (ty & 1), kx0 = 1 - (tx & 1);
    const int hy = (ty >> 1) + 1 + (ty & 1);
    const int hx = (tx >> 1) + 1 + (tx & 1);

    auto load_stage = [&](int cib, int buf) {
        #pragma unroll
        for (int cl = 0; cl < CIB; cl++) {
            const float* ip = inb + (size_t)(cib + cl)*HWin;
            float* sp = &sIn[buf][cl*IW*IWP];
            for (int r = ty2; r < IW; r += 8) {
                int gy = iyb + r;
                bool rowok = (unsigned)gy < (unsigned)Hin;
                const float* rp = ip + (size_t)gy*Win;
                for (int c = tx2; c < IW; c += 32) {
                    int gx = ixb + c;
                    cp4(sp + r*IWP + c, rp + gx,
                        rowok && ((unsigned)gx < (unsigned)Win));
                }
            }
        }
        for (int i = tid; i < CIB*16*OCBt; i += 256) {
            int oc = i & (OCBt-1);
            int rest = i >> LOG_OCB;
            int kk = rest & 15, cl = rest >> 4;
            cp4(&sWt[buf][i], wt + ((size_t)(cib+cl)*Cout + (ocb+oc))*16 + kk, true);
        }
    };

    unsigned long long acc2[OP][2][2];
    #pragma unroll
    for (int o = 0; o < OP; o++) {
        acc2[o][0][0] = 0ull; acc2[o][0][1] = 0ull;
        acc2[o][1][0] = 0ull; acc2[o][1][1] = 0ull;
    }

    const int NB = Cin / CIB;
    load_stage(0, 0);
    cp_commit();

    for (int b = 0; b < NB; b++) {
        const int buf = b & 1;
        if (b + 1 < NB) {
            load_stage((b+1)*CIB, buf ^ 1);
            cp_commit();
            cp_wait<1>();
        } else {
            cp_wait<0>();
        }
        __syncthreads();

        #pragma unroll
        for (int cl = 0; cl < CIB; cl++) {
            const float* sI = &sIn[buf][cl*IW*IWP];
            const float* sW = &sWt[buf][cl*16*OCBt];

            unsigned long long vin2[2][2][2][2];   // [ey][tap_y][ex][tap_x]
            #pragma unroll
            for (int ey = 0; ey < 2; ey++)
            #pragma unroll
            for (int tyt = 0; tyt < 2; tyt++)
            #pragma unroll
            for (int ex = 0; ex < 2; ex++)
            #pragma unroll
            for (int txt = 0; txt < 2; txt++) {
                float v = sI[(hy + 8*ey - tyt)*IWP + (hx + 8*ex - txt)];
                vin2[ey][tyt][ex][txt] = f2pack(v, v);
            }

            #pragma unroll
            for (int tyt = 0; tyt < 2; tyt++)
            #pragma unroll
            for (int txt = 0; txt < 2; txt++) {
                const int kk = (ky0 + 2*tyt)*4 + (kx0 + 2*txt);
                const unsigned long long* wp =
                    (const unsigned long long*)(sW + kk*OCBt);
                unsigned long long w2[OP];
                #pragma unroll
                for (int j = 0; j < OP; j++) w2[j] = wp[j];
                #pragma unroll
                for (int ey = 0; ey < 2; ey++)
                #pragma unroll
                for (int ex = 0; ex < 2; ex++) {
                    unsigned long long s2 = vin2[ey][tyt][ex][txt];
                    #pragma unroll
                    for (int o = 0; o < OP; o++)
                        acc2[o][ey][ex] = ffma2(w2[o], s2, acc2[o][ey][ex]);
                }
            }
        }
        __syncthreads();
    }

    #pragma unroll
    for (int o2 = 0; o2 < OP; o2++) {
        float accl[2][2][2];
        #pragma unroll
        for (int ey = 0; ey < 2; ey++)
        #pragma unroll
        for (int ex = 0; ex < 2; ex++) {
            float2 f = f2unpack(acc2[o2][ey][ex]);
            accl[0][ey][ex] = f.x; accl[1][ey][ex] = f.y;
        }
        #pragma unroll
        for (int h = 0; h < 2; h++) {
            int c = ocb + 2*o2 + h;
            float bv = bias ? __ldg(bias + c) : 0.f;
            #pragma unroll
            for (int ey = 0; ey < 2; ey++)
            #pragma unroll
            for (int ex = 0; ex < 2; ex++) {
                float v = accl[h][ey][ex];
                if (bias) v = __fadd_rn(v, bv);
                int oy = oy0 + ty + 16*ey, ox = ox0 + tx + 16*ex;
                if (act == 1)      v = (v > 0.f) ? v : __fmul_rn(0.01f, v);
                else if (act == 2) v = (v > 0.f) ? v : 0.f;
                out[(((size_t)n*Cout + c)*Hout + oy)*Wout + ox] = v;
            }
        }
    }
}

// ---------------- RVQ (numerics locked: identical value chains) ----------------
__global__ __launch_bounds__(256)
void cnorm_kernel(const float* __restrict__ cb, float* __restrict__ cn, int total)
{
    int warp = (blockIdx.x*256 + threadIdx.x) >> 5;
    int lane = threadIdx.x & 31;
    if (warp >= total) return;
    const float* p = cb + (size_t)warp*64;
    float a0 = p[lane], a1 = p[lane+32];
    float a = __fadd_rn(__fmul_rn(a0, a0), __fmul_rn(a1, a1));
    #pragma unroll
    for (int off = 16; off > 0; off >>= 1)
        a = __fadd_rn(a, __shfl_down_sync(0xffffffffu, a, off));
    if (lane == 0) cn[warp] = a;
}

// All 4 RVQ stages fused; dot products FFMA2-packed (each half-lane chain identical).
__global__ __launch_bounds__(256)
void rvq_fused(const float* __restrict__ r_in, float* __restrict__ qacc,
               const float* __restrict__ cbs, const float* __restrict__ cnorm,
               float* __restrict__ idx_out, float* __restrict__ partials, int HW)
{
    __shared__ __align__(16) float sCt[64*32];
    __shared__ float sCn[32];
    __shared__ float sRed[256];

    const int t = blockIdx.x*256 + threadIdx.x;
    const int n = t / HW, p = t - n*HW;
    const size_t base = (size_t)n*64*HW + p;

    float rl[64], qa[64];
    #pragma unroll
    for (int d = 0; d < 64; d++)
        rl[d] = r_in[base + (size_t)d*HW];

    for (int stage = 0; stage < 4; stage++) {
        const float* cb = cbs + (size_t)stage*512*64;
        const float* cn = cnorm + stage*512;

        float rn = 0.f;
        #pragma unroll
        for (int d = 0; d < 64; d++) rn = fmaf(rl[d], rl[d], rn);

        float best = 3.4e38f; int bidx = 0;
        for (int kb = 0; kb < 512; kb += 32) {
            __syncthreads();
            for (int i = threadIdx.x; i < 64*32; i += 256) {
                int kk = i & 31, d = i >> 5;
                sCt[i] = __ldg(cb + (size_t)(kb + kk)*64 + d);
            }
            if (threadIdx.x < 32) sCn[threadIdx.x] = cn[kb + threadIdx.x];
            __syncthreads();

            unsigned long long dot2[16];
            #pragma unroll
            for (int j = 0; j < 16; j++) dot2[j] = 0ull;
            #pragma unroll
            for (int d = 0; d < 64; d++) {
                unsigned long long rt2 = f2pack(rl[d], rl[d]);
                const ulonglong2* cp = (const ulonglong2*)(sCt + d*32);
                #pragma unroll
                for (int j4 = 0; j4 < 8; j4++) {
                    ulonglong2 c2 = cp[j4];
                    dot2[j4*2+0] = ffma2(rt2, c2.x, dot2[j4*2+0]);
                    dot2[j4*2+1] = ffma2(rt2, c2.y, dot2[j4*2+1]);
                }
            }
            #pragma unroll
            for (int j2 = 0; j2 < 16; j2++) {
                float2 dd = f2unpack(dot2[j2]);
                float dist0 = __fadd_rn(__fadd_rn(rn, -__fmul_rn(2.f, dd.x)), sCn[2*j2]);
                if (dist0 < best) { best = dist0; bidx = kb + 2*j2; }
                float dist1 = __fadd_rn(__fadd_rn(rn, -__fmul_rn(2.f, dd.y)), sCn[2*j2+1]);
                if (dist1 < best) { best = dist1; bidx = kb + 2*j2 + 1; }
            }
        }

        float lsum = 0.f;
        const float* cq = cb + (size_t)bidx*64;
        #pragma unroll
        for (int d = 0; d < 64; d++) {
            float q = __ldg(cq + d);
            float diff = __fadd_rn(q, -rl[d]);
            lsum = fmaf(diff, diff, lsum);
            float q_st = __fadd_rn(rl[d], diff);
            if (stage == 0) qa[d] = q_st;
            else            qa[d] = __fadd_rn(qa[d], q_st);
            rl[d] = __fadd_rn(rl[d], -q);
        }
        idx_out[(size_t)t*4 + stage] = (float)bidx;

        __syncthreads();
        sRed[threadIdx.x] = lsum;
        __syncthreads();
        for (int sft = 128; sft > 0; sft >>= 1) {
            if (threadIdx.x < sft) sRed[threadIdx.x] += sRed[threadIdx.x + sft];
            __syncthreads();
        }
        if (threadIdx.x == 0) partials[stage*256 + blockIdx.x] = sRed[0];
    }

    #pragma unroll
    for (int d = 0; d < 64; d++)
        qacc[base + (size_t)d*HW] = qa[d];
}

__global__ __launch_bounds__(256)
void loss_finalize(const float* __restrict__ partials, float* __restrict__ loss_out, float scale)
{
    __shared__ float sRed[256];
    int stage = blockIdx.x;
    sRed[threadIdx.x] = partials[stage*256 + threadIdx.x];
    __syncthreads();
    for (int sft = 128; sft > 0; sft >>= 1) {
        if (threadIdx.x < sft) sRed[threadIdx.x] += sRed[threadIdx.x + sft];
        __syncthreads();
    }
    if (threadIdx.x == 0) loss_out[stage] = 0.25f * (sRed[0] * scale);
}

// ---------------- launch ----------------
extern "C" void kernel_launch(void* const* d_in, const int* in_sizes, int n_in,
                              void* d_out, int out_size)
{
    const float* x     = (const float*)d_in[0];
    const float* e1w   = (const float*)d_in[1];
    const float* e1b   = (const float*)d_in[2];
    const float* e2w   = (const float*)d_in[3];
    const float* e2b   = (const float*)d_in[4];
    const float* e3w   = (const float*)d_in[5];
    const float* e3b   = (const float*)d_in[6];
    const float* r1aw  = (const float*)d_in[7];
    const float* r1bw  = (const float*)d_in[8];
    const float* r2aw  = (const float*)d_in[9];
    const float* r2bw  = (const float*)d_in[10];
    const float* e4w   = (const float*)d_in[11];
    const float* e4b   = (const float*)d_in[12];
    const float* cbs   = (const float*)d_in[13];
    const float* d1w   = (const float*)d_in[14];
    const float* d1b   = (const float*)d_in[15];
    const float* dr1aw = (const float*)d_in[16];
    const float* dr1bw = (const float*)d_in[17];
    const float* dr2aw = (const float*)d_in[18];
    const float* dr2bw = (const float*)d_in[19];
    const float* dt1w  = (const float*)d_in[20];
    const float* dt1b  = (const float*)d_in[21];
    const float* dt2w  = (const float*)d_in[22];
    const float* dt2b  = (const float*)d_in[23];

    float* out = (float*)d_out;
    float* recons  = out;                        // 16*4*256*256
    float* idxout  = out + (size_t)16*4*256*256; // 16*64*64*4
    float* lossout = idxout + (size_t)16*64*64*4;// 4

    float *A,*B,*C,*D,*R,*Q,*CN,*P;
    cudaGetSymbolAddress((void**)&A,  g_bufA);
    cudaGetSymbolAddress((void**)&B,  g_bufB);
    cudaGetSymbolAddress((void**)&C,  g_bufC);
    cudaGetSymbolAddress((void**)&D,  g_bufD);
    cudaGetSymbolAddress((void**)&R,  g_r);
    cudaGetSymbolAddress((void**)&Q,  g_q);
    cudaGetSymbolAddress((void**)&CN, g_cnorm);
    cudaGetSymbolAddress((void**)&P,  g_partials);

    cnorm_kernel<<<256, 256>>>(cbs, CN, 4*512);

    // ---- encoder (fp32, numerics locked) ----
    conv_pipe<4,2,1><<<dim3(4,4,64), 256>>>(x, e1w, e1b, nullptr, A,
                                            16,4,256,256, 64,128,128, 1, 1);
    conv_pipe<4,2,1><<<dim3(2,2,128), 256>>>(A, e2w, e2b, nullptr, B,
                                             16,64,128,128, 128,64,64, 1, 1);
    conv_pipe<3,1,4><<<dim3(2,2,128), 256>>>(B, e3w, e3b, nullptr, C,
                                             16,128,64,64, 128,64,64, 1, 1);
    conv_pipe<3,1,4><<<dim3(2,2,128), 256>>>(C, r1aw, nullptr, nullptr, D,
                                             16,128,64,64, 128,64,64, 1, 2);
    conv1x1<<<dim3(64,8), 256>>>(D, r1bw, nullptr, C, B, 128, 4096, 128, 0);
    conv_pipe<3,1,4><<<dim3(2,2,128), 256>>>(B, r2aw, nullptr, nullptr, D,
                                             16,128,64,64, 128,64,64, 1, 2);
    conv1x1<<<dim3(64,8), 256>>>(D, r2bw, nullptr, B, C, 128, 4096, 128, 1);
    conv1x1<<<dim3(64,4), 256>>>(C, e4w, e4b, nullptr, R, 128, 4096, 64, 1);

    // ---- residual VQ: 4 stages fused ----
    rvq_fused<<<256, 256>>>(R, Q, cbs, CN, idxout, P, 64*64);
    loss_finalize<<<4, 256>>>(P, lossout, 1.f/(65536.f*64.f));

    // ---- decoder (fp32, numerics locked) ----
    conv_pipe<3,1,4><<<dim3(2,2,128), 256>>>(Q, d1w, d1b, nullptr, B,
                                             16,64,64,64, 128,64,64, 1, 1);
    conv_pipe<3,1,4><<<dim3(2,2,128), 256>>>(B, dr1aw, nullptr, nullptr, D,
                                             16,128,64,64, 128,64,64, 1, 2);
    conv1x1<<<dim3(64,8), 256>>>(D, dr1bw, nullptr, B, C, 128, 4096, 128, 0);
    conv_pipe<3,1,4><<<dim3(2,2,128), 256>>>(C, dr2aw, nullptr, nullptr, D,
                                             16,128,64,64, 128,64,64, 1, 2);
    conv1x1<<<dim3(64,8), 256>>>(D, dr2bw, nullptr, C, B, 128, 4096, 128, 1);
    convT_pipe<16,4,8><<<dim3(4,4,64), 256>>>(B, dt1w, dt1b, A,
                                              16,128,64,64, 64, 1);
    convT_pipe<4,2,8><<<dim3(8,8,16), 256>>>(A, dt2w, dt2b, recons,
                                             16,64,128,128, 4, 2);
}